// round 4
// baseline (speedup 1.0000x reference)
#include <cuda_runtime.h>

// Problem constants (from reference): B=64, T=512, E=8192
// out[b][j] = (1/count) * sum_{r=r0}^{T-1} x[b*T*E + (j+T) + r*(E-1)]
//   where r0 = max(0, j - (E - T - 1)), count = T - r0, j in [0, E-2].

#define B_DIM 64
#define T_DIM 512
#define E_DIM 8192
#define OUT_COLS (E_DIM - 1)          // 8191
#define ROW_STRIDE (E_DIM - 1)        // stride between consecutive r on a diagonal
#define J_FULL (E_DIM - T_DIM - 1)    // 7679: j <= J_FULL has full 512-count

__global__ __launch_bounds__(256) void antidiag_mean_kernel(
    const float* __restrict__ x, float* __restrict__ out)
{
    const int j = blockIdx.x * blockDim.x + threadIdx.x;
    const int b = blockIdx.y;
    if (j >= OUT_COLS) return;

    // Base points at r=0 element of this diagonal: x[b][0][j+T]
    const float* base = x + (size_t)b * T_DIM * E_DIM + (size_t)(j + T_DIM);

    const int r0 = (j > J_FULL) ? (j - J_FULL) : 0;
    const int count = T_DIM - r0;

    float sum = 0.0f;
    // Each warp iteration reads 32 consecutive floats of row r -> coalesced.
    // unroll 16 front-batches 16 independent LDGs per scoreboard drain (MLP).
    #pragma unroll 16
    for (int r = r0; r < T_DIM; ++r) {
        sum += base[(size_t)r * ROW_STRIDE];
    }

    out[(size_t)b * OUT_COLS + j] = sum * (1.0f / (float)count);
}

extern "C" void kernel_launch(void* const* d_in, const int* in_sizes, int n_in,
                              void* d_out, int out_size)
{
    const float* x = (const float*)d_in[0];
    float* out = (float*)d_out;

    dim3 block(256);
    dim3 grid((OUT_COLS + 255) / 256, B_DIM);
    antidiag_mean_kernel<<<grid, block>>>(x, out);
}

// round 5
// speedup vs baseline: 1.3611x; 1.3611x over previous
#include <cuda_runtime.h>

// B=64, T=512, E=8192
// out[b][j] = (1/count) * sum_{r=r0}^{511} x[b*T*E + (j+512) + r*8191]
//   r0 = max(0, j - 7679), count = 512 - r0, j in [0, 8190].

#define B_DIM 64
#define T_DIM 512
#define E_DIM 8192
#define OUT_COLS (E_DIM - 1)          // 8191
#define ROW_STRIDE (E_DIM - 1)        // 8191 floats between consecutive r
#define J_FULL (E_DIM - T_DIM - 1)    // 7679
#define TILE_W 512                    // outputs per CTA (2 per thread)
#define NUM_TILES (E_DIM / TILE_W)    // 16; last tile holds the ragged tail

__global__ __launch_bounds__(256) void antidiag_mean_kernel(
    const float* __restrict__ x, float* __restrict__ out)
{
    const int tid = threadIdx.x;
    const int b   = blockIdx.y;
    const int j0  = blockIdx.x * TILE_W;
    const int j_a = j0 + tid;          // [j0, j0+255]
    const int j_b = j0 + tid + 256;    // [j0+256, j0+511]

    const float* __restrict__ xb = x + (size_t)b * T_DIM * E_DIM;
    float* __restrict__ ob = out + (size_t)b * OUT_COLS;

    if (blockIdx.x < NUM_TILES - 1) {
        // ---- hot path: both streams have full count = 512 (j <= 7679) ----
        const float* pa = xb + (j_a + T_DIM);
        const float* pb = xb + (j_b + T_DIM);
        float s0 = 0.0f, s1 = 0.0f;
        // 16 independent LDGs per unrolled batch, two independent add chains.
        // 32-bit offsets: max byte offset 511*8191*4 = 16.7MB < 2^31.
        #pragma unroll 8
        for (int r = 0; r < T_DIM; ++r) {
            const unsigned off = (unsigned)(r * ROW_STRIDE);
            s0 += pa[off];
            s1 += pb[off];
        }
        ob[j_a] = s0 * (1.0f / (float)T_DIM);
        ob[j_b] = s1 * (1.0f / (float)T_DIM);
    } else {
        // ---- tail tile (j in [7680, 8190]): ragged counts, 1/16 of columns ----
        {
            const int r0 = (j_a > J_FULL) ? (j_a - J_FULL) : 0;
            const float* pa = xb + (j_a + T_DIM);
            float s = 0.0f;
            #pragma unroll 8
            for (int r = r0; r < T_DIM; ++r)
                s += pa[(unsigned)(r * ROW_STRIDE)];
            ob[j_a] = s * (1.0f / (float)(T_DIM - r0));
        }
        if (j_b < OUT_COLS) {
            const int r0 = (j_b > J_FULL) ? (j_b - J_FULL) : 0;
            const float* pb = xb + (j_b + T_DIM);
            float s = 0.0f;
            #pragma unroll 8
            for (int r = r0; r < T_DIM; ++r)
                s += pb[(unsigned)(r * ROW_STRIDE)];
            ob[j_b] = s * (1.0f / (float)(T_DIM - r0));
        }
    }
}

extern "C" void kernel_launch(void* const* d_in, const int* in_sizes, int n_in,
                              void* d_out, int out_size)
{
    const float* x = (const float*)d_in[0];
    float* out = (float*)d_out;

    dim3 block(256);
    dim3 grid(NUM_TILES, B_DIM);   // 16 x 64 = 1024 CTAs
    antidiag_mean_kernel<<<grid, block>>>(x, out);
}

// round 6
// speedup vs baseline: 1.3943x; 1.0244x over previous
#include <cuda_runtime.h>

// B=64, T=512, E=8192
// out[b][j] = (1/count) * sum_{r=r0}^{511} x[b*T*E + (j+512) + r*8191]
//   r0 = max(0, j - 7679), count = 512 - r0, j in [0, 8190].

#define B_DIM 64
#define T_DIM 512
#define E_DIM 8192
#define OUT_COLS (E_DIM - 1)          // 8191
#define ROW_STRIDE (E_DIM - 1)        // 8191 floats between consecutive r
#define J_FULL (E_DIM - T_DIM - 1)    // 7679
#define TILE_W 512                    // outputs per CTA (2 per thread)
#define NUM_TILES (E_DIM / TILE_W)    // 16; last tile holds the ragged tail
#define R_HALF (T_DIM / 2)            // 256

__global__ __launch_bounds__(256) void antidiag_mean_kernel(
    const float* __restrict__ x, float* __restrict__ out)
{
    const int tid = threadIdx.x;
    const int b   = blockIdx.y;
    const int j0  = blockIdx.x * TILE_W;
    const int j_a = j0 + tid;          // [j0, j0+255]
    const int j_b = j0 + tid + 256;    // [j0+256, j0+511]

    const float* __restrict__ xb = x + (size_t)b * T_DIM * E_DIM;
    float* __restrict__ ob = out + (size_t)b * OUT_COLS;

    if (blockIdx.x < NUM_TILES - 1) {
        // ---- hot path: full count = 512 for both j streams (j <= 7679) ----
        // 4 independent streams: {j_a, j_b} x {r lower half, r upper half}.
        // unroll 8 -> 32 independent LDGs per scoreboard window.
        const float* pa_lo = xb + (j_a + T_DIM);
        const float* pb_lo = xb + (j_b + T_DIM);
        const float* pa_hi = pa_lo + (size_t)R_HALF * ROW_STRIDE;
        const float* pb_hi = pb_lo + (size_t)R_HALF * ROW_STRIDE;

        float s0_lo = 0.0f, s0_hi = 0.0f, s1_lo = 0.0f, s1_hi = 0.0f;
        #pragma unroll 8
        for (int r = 0; r < R_HALF; ++r) {
            const unsigned off = (unsigned)(r * ROW_STRIDE);  // max 16.7MB < 2^31
            s0_lo += pa_lo[off];
            s0_hi += pa_hi[off];
            s1_lo += pb_lo[off];
            s1_hi += pb_hi[off];
        }
        ob[j_a] = (s0_lo + s0_hi) * (1.0f / (float)T_DIM);
        ob[j_b] = (s1_lo + s1_hi) * (1.0f / (float)T_DIM);
    } else {
        // ---- tail tile (j in [7680, 8190]): ragged counts, 1/16 of columns ----
        {
            const int r0 = (j_a > J_FULL) ? (j_a - J_FULL) : 0;
            const float* pa = xb + (j_a + T_DIM);
            float s = 0.0f;
            #pragma unroll 8
            for (int r = r0; r < T_DIM; ++r)
                s += pa[(unsigned)(r * ROW_STRIDE)];
            ob[j_a] = s * (1.0f / (float)(T_DIM - r0));
        }
        if (j_b < OUT_COLS) {
            const int r0 = (j_b > J_FULL) ? (j_b - J_FULL) : 0;
            const float* pb = xb + (j_b + T_DIM);
            float s = 0.0f;
            #pragma unroll 8
            for (int r = r0; r < T_DIM; ++r)
                s += pb[(unsigned)(r * ROW_STRIDE)];
            ob[j_b] = s * (1.0f / (float)(T_DIM - r0));
        }
    }
}

extern "C" void kernel_launch(void* const* d_in, const int* in_sizes, int n_in,
                              void* d_out, int out_size)
{
    const float* x = (const float*)d_in[0];
    float* out = (float*)d_out;

    dim3 block(256);
    dim3 grid(NUM_TILES, B_DIM);   // 16 x 64 = 1024 CTAs
    antidiag_mean_kernel<<<grid, block>>>(x, out);
}